// round 2
// baseline (speedup 1.0000x reference)
#include <cuda_runtime.h>
#include <cuda_fp16.h>
#include <cstdint>

// ============================================================================
// Problem constants
// ============================================================================
#define DK 4096            // D_IN  (K)
#define DN 4096            // D_OUT (N)
#define DM 4096            // B*S   (M)
#define NELEM_W (16777216) // 4096*4096

// ============================================================================
// Scratch (device globals — no allocations allowed)
// ============================================================================
__device__ unsigned long long g_sum_abs;               // sum |wf|
__device__ __half g_B  [(size_t)DN * DK];              // ternary weights as fp16
__device__ __half g_Alo[(size_t)DM * DK];              // low  limb of xq  [-1024,1023]
__device__ __half g_Ahi[(size_t)DM * DK];              // high limb of xq  (q-lo)>>11

// ============================================================================
// Small PTX helpers (base-target only: cp.async / ldmatrix / mma.sync)
// ============================================================================
__device__ __forceinline__ uint32_t smem_to_u32(const void* p) {
    uint32_t a;
    asm("{ .reg .u64 t; cvta.to.shared.u64 t, %1; cvt.u32.u64 %0, t; }" : "=r"(a) : "l"(p));
    return a;
}

__device__ __forceinline__ void cp_async16(uint32_t smaddr, const void* gptr) {
    asm volatile("cp.async.cg.shared.global [%0], [%1], 16;" :: "r"(smaddr), "l"(gptr));
}
__device__ __forceinline__ void cp_commit() {
    asm volatile("cp.async.commit_group;");
}
template <int N>
__device__ __forceinline__ void cp_wait() {
    asm volatile("cp.async.wait_group %0;" :: "n"(N));
}

__device__ __forceinline__ void ldsm_x4(uint32_t (&r)[4], uint32_t addr) {
    asm volatile("ldmatrix.sync.aligned.m8n8.x4.shared.b16 {%0,%1,%2,%3}, [%4];"
        : "=r"(r[0]), "=r"(r[1]), "=r"(r[2]), "=r"(r[3]) : "r"(addr));
}

__device__ __forceinline__ void mma_16816(float (&c)[4], const uint32_t (&a)[4],
                                          const uint32_t* b) {
    asm volatile(
        "mma.sync.aligned.m16n8k16.row.col.f32.f16.f16.f32 "
        "{%0,%1,%2,%3}, {%4,%5,%6,%7}, {%8,%9}, {%0,%1,%2,%3};"
        : "+f"(c[0]), "+f"(c[1]), "+f"(c[2]), "+f"(c[3])
        : "r"(a[0]), "r"(a[1]), "r"(a[2]), "r"(a[3]), "r"(b[0]), "r"(b[1]));
}

// ============================================================================
// Kernel 1: zero the reduction accumulator
// ============================================================================
__global__ void zero_kernel() { g_sum_abs = 0ull; }

// ============================================================================
// Kernel 2: sum |round(w * 2^16)| over all weights (exact integer reduction)
// ============================================================================
__global__ void reduce_abs_kernel(const float* __restrict__ w) {
    long long s = 0;
    int stride = gridDim.x * blockDim.x;
    for (int i = blockIdx.x * blockDim.x + threadIdx.x; i < NELEM_W; i += stride) {
        long long v = llrintf(w[i] * 65536.0f);   // RNE == jnp.round
        s += v < 0 ? -v : v;
    }
    #pragma unroll
    for (int o = 16; o > 0; o >>= 1) s += __shfl_down_sync(0xffffffffu, s, o);
    __shared__ long long ws[8];
    if ((threadIdx.x & 31) == 0) ws[threadIdx.x >> 5] = s;
    __syncthreads();
    if (threadIdx.x < 8) {
        s = ws[threadIdx.x];
        #pragma unroll
        for (int o = 4; o > 0; o >>= 1) s += __shfl_down_sync(0xffu, s, o);
        if (threadIdx.x == 0) atomicAdd(&g_sum_abs, (unsigned long long)s);
    }
}

// ============================================================================
// Kernel 3: ternarize weights -> fp16 {-1,0,1}
// clip(floor(wf / mean_abs), -1, 1):  wf>=mean -> 1, wf<0 -> -1, else 0
// ============================================================================
__global__ void ternary_kernel(const float* __restrict__ w) {
    long long mean_abs = (long long)(g_sum_abs >> 24);  // // 2^24 elements
    if (mean_abs < 1) mean_abs = 1;
    size_t i = (size_t)blockIdx.x * blockDim.x + threadIdx.x;
    long long wf = llrintf(w[i] * 65536.0f);
    int t = (wf >= mean_abs) ? 1 : ((wf < 0) ? -1 : 0);
    g_B[i] = __int2half_rn(t);
}

// ============================================================================
// Kernel 4: per-row activation quant (exact Q16.16) + limb split to fp16
// ============================================================================
__global__ void actquant_kernel(const float* __restrict__ x) {
    __shared__ long long red[256];
    int r = blockIdx.x;
    const float* xr = x + (size_t)r * DK;

    long long mymax = 0;
    for (int i = threadIdx.x; i < DK; i += 256) {
        long long v = llrintf(xr[i] * 65536.0f);
        if (v < 0) v = -v;
        if (v > mymax) mymax = v;
    }
    red[threadIdx.x] = mymax;
    __syncthreads();
    #pragma unroll
    for (int s = 128; s > 0; s >>= 1) {
        if (threadIdx.x < s) {
            long long a = red[threadIdx.x], b = red[threadIdx.x + s];
            red[threadIdx.x] = a > b ? a : b;
        }
        __syncthreads();
    }
    long long maxv = red[0];
    if (maxv < 1) maxv = 1;
    long long scale     = ((long long)127 << 32) / maxv;   // (127<<16<<16)//maxv
    long long scale_inv = ((long long)1 << 32) / scale;    // 2^32 // scale

    for (int i = threadIdx.x; i < DK; i += 256) {
        long long xf = llrintf(xr[i] * 65536.0f);
        long long xs = (xf * scale) >> 16;                 // arith shift == floor
        if (xs >  8323072ll) xs =  8323072ll;              //  127<<16
        if (xs < -8388608ll) xs = -8388608ll;              // -(128<<16)
        long long xq = (xs * scale_inv) >> 16;
        int q  = (int)xq;
        int lo = ((q + 1024) & 2047) - 1024;               // balanced mod 2048
        int hi = (q - lo) >> 11;
        size_t o = (size_t)r * DK + i;
        g_Alo[o] = __int2half_rn(lo);
        g_Ahi[o] = __int2half_rn(hi);
    }
}

// ============================================================================
// Kernel 5: fp16 mma.sync GEMM.
//   CTA tile 128x128, 8 warps (4x2), warp tile 32x64, dual accumulators
//   (lo & hi limb). 4-stage cp.async pipeline, K-chunk = 64 halves.
//   SMEM rows have 144B pitch (9 x 16B): ldmatrix bank-group = (9r+c)&7,
//   a permutation over 8 rows -> conflict-free.
// ============================================================================
static constexpr int ROWP    = 144;                 // bytes per 64-half row (padded)
static constexpr int STAGE_B = 384 * ROWP;          // Alo(128)+Ahi(128)+B(128) rows
static constexpr int NSTAGE  = 4;
static constexpr int SMEM_SZ = NSTAGE * STAGE_B;    // 221184 B
static constexpr int NCHUNK  = DK / 64;             // 64

__device__ __forceinline__ void issue_chunk_loads(
    uint32_t smem_base, int stage, int kk, int m0, int n0, int tid)
{
    uint32_t sb = smem_base + stage * STAGE_B;
    int khalf = kk * 64;
    #pragma unroll
    for (int t = 0; t < 12; t++) {
        int idx = tid + t * 256;        // 3072 16B chunks per stage
        int row = idx >> 3;             // 0..383
        int c   = idx & 7;              // 16B chunk within 64-half row
        int mat = row >> 7;             // 0:Alo 1:Ahi 2:B
        int r   = row & 127;
        const __half* base = (mat == 0) ? g_Alo : (mat == 1) ? g_Ahi : g_B;
        int gr = ((mat == 2) ? n0 : m0) + r;
        const __half* src = base + (size_t)gr * DK + khalf + c * 8;
        cp_async16(sb + row * ROWP + c * 16, src);
    }
    cp_commit();
}

__global__ void __launch_bounds__(256, 1) gemm_kernel(float* __restrict__ out) {
    extern __shared__ __align__(1024) char smem[];
    uint32_t smem_base = smem_to_u32(smem);
    int tid  = threadIdx.x;
    int wid  = tid >> 5, lane = tid & 31;
    int m0   = blockIdx.y * 128, n0 = blockIdx.x * 128;
    int m_w  = (wid >> 1) * 32;          // warp row offset in tile
    int n_w  = (wid & 1) * 64;           // warp col offset in tile

    // Per-thread invariant ldmatrix offsets (within a stage)
    uint32_t a_off[2][2];
    #pragma unroll
    for (int L = 0; L < 2; L++)
        #pragma unroll
        for (int mt = 0; mt < 2; mt++)
            a_off[L][mt] = (uint32_t)((L * 128 + m_w + mt * 16 + (lane & 15)) * ROWP
                                      + (lane >> 4) * 16);
    uint32_t b_off[4];
    #pragma unroll
    for (int p = 0; p < 4; p++)
        b_off[p] = (uint32_t)((256 + n_w + p * 16 + ((lane >> 4) << 3) + (lane & 7)) * ROWP
                              + ((lane >> 3) & 1) * 16);

    float acc[2][2][8][4];
    #pragma unroll
    for (int L = 0; L < 2; L++)
        #pragma unroll
        for (int mt = 0; mt < 2; mt++)
            #pragma unroll
            for (int nt = 0; nt < 8; nt++)
                #pragma unroll
                for (int i = 0; i < 4; i++) acc[L][mt][nt][i] = 0.0f;

    // Prologue: 3 chunks in flight
    issue_chunk_loads(smem_base, 0, 0, m0, n0, tid);
    issue_chunk_loads(smem_base, 1, 1, m0, n0, tid);
    issue_chunk_loads(smem_base, 2, 2, m0, n0, tid);

    for (int kk = 0; kk < NCHUNK; kk++) {
        if (kk + 3 < NCHUNK) cp_wait<2>(); else cp_wait<0>();
        __syncthreads();
        if (kk + 3 < NCHUNK)
            issue_chunk_loads(smem_base, (kk + 3) & 3, kk + 3, m0, n0, tid);

        uint32_t sb = smem_base + (kk & 3) * STAGE_B;
        #pragma unroll
        for (int ks = 0; ks < 4; ks++) {       // 4 k16-steps per 64-half chunk
            uint32_t af[2][2][4];
            #pragma unroll
            for (int L = 0; L < 2; L++)
                #pragma unroll
                for (int mt = 0; mt < 2; mt++)
                    ldsm_x4(af[L][mt], sb + a_off[L][mt] + ks * 32);
            uint32_t bf[8][2];
            #pragma unroll
            for (int p = 0; p < 4; p++) {
                uint32_t r4[4];
                ldsm_x4(r4, sb + b_off[p] + ks * 32);
                bf[2 * p][0] = r4[0]; bf[2 * p][1] = r4[1];
                bf[2 * p + 1][0] = r4[2]; bf[2 * p + 1][1] = r4[3];
            }
            #pragma unroll
            for (int L = 0; L < 2; L++)
                #pragma unroll
                for (int mt = 0; mt < 2; mt++)
                    #pragma unroll
                    for (int nt = 0; nt < 8; nt++)
                        mma_16816(acc[L][mt][nt], af[L][mt], bf[nt]);
        }
        __syncthreads();
    }

    // Epilogue: combine limbs, wrap to int32, dequantize, write float
    long long mean_abs = (long long)(g_sum_abs >> 24);
    if (mean_abs < 1) mean_abs = 1;
    long long sinv = ((long long)1 << 32) / mean_abs;    // fixed_reciprocal
    int g = lane >> 2, t4 = lane & 3;

    #pragma unroll
    for (int mt = 0; mt < 2; mt++) {
        #pragma unroll
        for (int nt = 0; nt < 8; nt++) {
            int n = n0 + n_w + nt * 8 + t4 * 2;
            #pragma unroll
            for (int half = 0; half < 2; half++) {       // c0,c1 then c2,c3
                int m = m0 + m_w + mt * 16 + g + half * 8;
                float2 o2;
                #pragma unroll
                for (int u = 0; u < 2; u++) {
                    long long a = (long long)acc[0][mt][nt][half * 2 + u]
                                + ((long long)acc[1][mt][nt][half * 2 + u] << 11);
                    int a32 = (int)a;                          // int32 wrap
                    long long v = ((long long)a32 * sinv) >> 16;
                    (&o2.x)[u] = (float)v * (1.0f / 65536.0f);
                }
                *reinterpret_cast<float2*>(out + (size_t)m * DN + n) = o2;
            }
        }
    }
}

// ============================================================================
// Launcher (graph-capturable: kernel launches only)
// ============================================================================
extern "C" void kernel_launch(void* const* d_in, const int* in_sizes, int n_in,
                              void* d_out, int out_size) {
    const float* x = (const float*)d_in[0];     // [2,2048,4096]
    const float* w = (const float*)d_in[1];     // [4096,4096]
    float* out = (float*)d_out;                 // [2,2048,4096]

    cudaFuncSetAttribute(gemm_kernel, cudaFuncAttributeMaxDynamicSharedMemorySize, SMEM_SZ);

    zero_kernel<<<1, 1>>>();
    reduce_abs_kernel<<<2048, 256>>>(w);
    ternary_kernel<<<NELEM_W / 256, 256>>>(w);
    actquant_kernel<<<DM, 256>>>(x);
    dim3 grid(DN / 128, DM / 128);
    gemm_kernel<<<grid, 256, SMEM_SZ>>>(out);
}